// round 4
// baseline (speedup 1.0000x reference)
#include <cuda_runtime.h>
#include <stdint.h>

// RadarDopSparseProcessor — exact 0.9-quantile threshold + ordered compaction.
// B=4, N=40*320*320=4,096,000 per batch. thr = order statistic at rank
// floor(0.9f*(N-1)); frac handled exactly like jnp.quantile('linear').

#define Bn 4
#define Zd 40
#define Yd 320
#define Xd 320
#define Nv (Zd*Yd*Xd)            // 4,096,000
#define Kpad (Nv/10 + 64)        // 409,664
#define BKr (Bn*Kpad)            // 1,638,656
#define VEC_PER_BATCH (Nv/4)     // 1,024,000 float4s

#define H1_BINS 4096
#define H2_BINS 4096
#define H3_BINS 256

#define HV_BLOCKS 37             // 37*4 = 148 blocks = 1/SM
#define VPB 27676                // ceil(1024000/37)

#define SC_BLOCKS 250            // per batch; 250*16384 = 4,096,000
#define SC_THREADS 512

__device__ unsigned g_hist1[Bn][H1_BINS];
__device__ unsigned g_hist2[Bn][2][H2_BINS];
__device__ unsigned g_hist3[Bn][2][H3_BINS];
__device__ unsigned g_sel1[Bn][2];
__device__ unsigned g_rem1[Bn][2];
__device__ unsigned g_sel2[Bn][2];
__device__ unsigned g_rem2[Bn][2];
__device__ float    g_thr[Bn];
__device__ unsigned long long g_part[Bn][SC_BLOCKS];
__device__ unsigned g_total[Bn];

__device__ __forceinline__ unsigned warp_iscan(unsigned v){
  #pragma unroll
  for (int d=1; d<32; d<<=1){
    unsigned n = __shfl_up_sync(0xFFFFFFFFu, v, d);
    if ((threadIdx.x & 31) >= d) v += n;
  }
  return v;
}

__global__ __launch_bounds__(1024) void k_zero(){
  int i = blockIdx.x*1024 + threadIdx.x;
  if (i < Bn*H1_BINS)     (&g_hist1[0][0])[i] = 0u;
  if (i < Bn*2*H2_BINS)   (&g_hist2[0][0][0])[i] = 0u;
  if (i < Bn*2*H3_BINS)   (&g_hist3[0][0][0])[i] = 0u;
  if (i < Bn*SC_BLOCKS)   (&g_part[0][0])[i] = 0ull;
  if (i < Bn)             g_total[i] = 0u;
}

// ---------------- pass 1: 12-bit histogram (bits 31..20), MLP=4 ----------------
__device__ __forceinline__ void h1add(unsigned* h, float f){
  atomicAdd(&h[__float_as_uint(f)>>20], 1u);
}
__device__ __forceinline__ void h1add4(unsigned* h, float4 v){
  h1add(h,v.x); h1add(h,v.y); h1add(h,v.z); h1add(h,v.w);
}
__global__ __launch_bounds__(1024) void k_hist1(const float* __restrict__ cube){
  __shared__ unsigned hist[H1_BINS];
  int b = blockIdx.y;
  int start = blockIdx.x * VPB;
  int n = min(VPB, VEC_PER_BATCH - start);
  const float4* p = (const float4*)cube + (size_t)b*VEC_PER_BATCH + start;
  for (int i=threadIdx.x;i<H1_BINS;i+=1024) hist[i]=0u;
  __syncthreads();
  int i = threadIdx.x;
  for (; i + 3072 < n; i += 4096){
    float4 v0=p[i], v1=p[i+1024], v2=p[i+2048], v3=p[i+3072];
    h1add4(hist,v0); h1add4(hist,v1); h1add4(hist,v2); h1add4(hist,v3);
  }
  for (; i < n; i += 1024) h1add4(hist, p[i]);
  __syncthreads();
  for (int k=threadIdx.x;k<H1_BINS;k+=1024){
    unsigned c=hist[k];
    if (c) atomicAdd(&g_hist1[b][k], c);
  }
}

__global__ __launch_bounds__(1024) void k_select1(){
  int b = blockIdx.x; int tid = threadIdx.x;
  __shared__ unsigned s[H1_BINS];
  __shared__ unsigned wq[32];
  for (int i=tid;i<H1_BINS;i+=1024) s[i]=g_hist1[b][i];
  __syncthreads();
  unsigned l0=s[tid*4+0],l1=s[tid*4+1],l2=s[tid*4+2],l3=s[tid*4+3];
  unsigned sum=l0+l1+l2+l3;
  unsigned inc=warp_iscan(sum);
  if((tid&31)==31) wq[tid>>5]=inc;
  __syncthreads();
  if(tid==0){unsigned run=0; for(int k=0;k<32;k++){unsigned t=wq[k];wq[k]=run;run+=t;}}
  __syncthreads();
  unsigned excl = inc - sum + wq[tid>>5];
  const float pos = 0.9f * (float)(Nv-1);
  unsigned r0 = (unsigned)floorf(pos);
  unsigned r1 = (unsigned)ceilf(pos); if (r1 > Nv-1) r1 = Nv-1;
  unsigned ranks[2] = {r0, r1};
  for (int j=0;j<2;j++){
    unsigned r = ranks[j];
    if (r>=excl && r<excl+sum){
      unsigned c=excl; unsigned loc[4]={l0,l1,l2,l3};
      #pragma unroll
      for(int k2=0;k2<4;k2++){
        if (r < c+loc[k2]){ g_sel1[b][j]=(unsigned)(tid*4+k2); g_rem1[b][j]=r-c; break; }
        c+=loc[k2];
      }
    }
  }
}

// ---------------- pass 2: 12-bit (bits 19..8) restricted, MLP=4 ----------------
__device__ __forceinline__ void h2add(unsigned* h0, unsigned* h1, unsigned sA, unsigned sB, float f){
  unsigned u=__float_as_uint(f); unsigned t=u>>20;
  if (t==sA) atomicAdd(&h0[(u>>8)&0xFFFu],1u);
  else if (t==sB) atomicAdd(&h1[(u>>8)&0xFFFu],1u);
}
__device__ __forceinline__ void h2add4(unsigned* h0, unsigned* h1, unsigned sA, unsigned sB, float4 v){
  h2add(h0,h1,sA,sB,v.x); h2add(h0,h1,sA,sB,v.y); h2add(h0,h1,sA,sB,v.z); h2add(h0,h1,sA,sB,v.w);
}
__global__ __launch_bounds__(1024) void k_hist2(const float* __restrict__ cube){
  __shared__ unsigned hist[2][H2_BINS];
  int b=blockIdx.y;
  unsigned sA=g_sel1[b][0], sB=g_sel1[b][1];
  for (int i=threadIdx.x;i<2*H2_BINS;i+=1024) (&hist[0][0])[i]=0u;
  __syncthreads();
  int start = blockIdx.x * VPB;
  int n = min(VPB, VEC_PER_BATCH - start);
  const float4* p=(const float4*)cube + (size_t)b*VEC_PER_BATCH + start;
  int i = threadIdx.x;
  for (; i + 3072 < n; i += 4096){
    float4 v0=p[i], v1=p[i+1024], v2=p[i+2048], v3=p[i+3072];
    h2add4(hist[0],hist[1],sA,sB,v0); h2add4(hist[0],hist[1],sA,sB,v1);
    h2add4(hist[0],hist[1],sA,sB,v2); h2add4(hist[0],hist[1],sA,sB,v3);
  }
  for (; i < n; i += 1024) h2add4(hist[0],hist[1],sA,sB,p[i]);
  __syncthreads();
  for (int k=threadIdx.x;k<2*H2_BINS;k+=1024){
    unsigned c=(&hist[0][0])[k];
    if (c) atomicAdd((&g_hist2[b][0][0])+k, c);
  }
}

__global__ __launch_bounds__(1024) void k_select2(){
  int b=blockIdx.x; int tid=threadIdx.x;
  __shared__ unsigned s[H2_BINS];
  __shared__ unsigned wq[32];
  unsigned sA=g_sel1[b][0], sB=g_sel1[b][1];
  bool same = (sA==sB);
  int np = same?1:2;
  for (int p=0;p<np;p++){
    for (int i=tid;i<H2_BINS;i+=1024) s[i]=g_hist2[b][p][i];
    __syncthreads();
    unsigned l0=s[tid*4+0],l1=s[tid*4+1],l2=s[tid*4+2],l3=s[tid*4+3];
    unsigned sum=l0+l1+l2+l3;
    unsigned inc=warp_iscan(sum);
    if((tid&31)==31) wq[tid>>5]=inc;
    __syncthreads();
    if(tid==0){unsigned run=0; for(int k=0;k<32;k++){unsigned t=wq[k];wq[k]=run;run+=t;}}
    __syncthreads();
    unsigned excl = inc - sum + wq[tid>>5];
    for (int j=0;j<2;j++){
      bool act = same ? (p==0) : (j==p);
      if (act){
        unsigned r=g_rem1[b][j];
        if (r>=excl && r<excl+sum){
          unsigned c=excl; unsigned loc[4]={l0,l1,l2,l3};
          #pragma unroll
          for(int k2=0;k2<4;k2++){
            if (r < c+loc[k2]){ g_sel2[b][j]=(g_sel1[b][j]<<12)|(unsigned)(tid*4+k2); g_rem2[b][j]=r-c; break; }
            c+=loc[k2];
          }
        }
      }
    }
    __syncthreads();
  }
}

// ---------------- pass 3: 8-bit (bits 7..0) restricted, MLP=4 ----------------
__device__ __forceinline__ void h3add(int b, unsigned p0, unsigned p1, float f){
  unsigned u=__float_as_uint(f); unsigned pre=u>>8;
  if (pre==p0) atomicAdd(&g_hist3[b][0][u&0xFFu],1u);
  else if (pre==p1) atomicAdd(&g_hist3[b][1][u&0xFFu],1u);
}
__device__ __forceinline__ void h3add4(int b, unsigned p0, unsigned p1, float4 v){
  h3add(b,p0,p1,v.x); h3add(b,p0,p1,v.y); h3add(b,p0,p1,v.z); h3add(b,p0,p1,v.w);
}
__global__ __launch_bounds__(1024) void k_hist3(const float* __restrict__ cube){
  int b=blockIdx.y;
  unsigned p0=g_sel2[b][0], p1=g_sel2[b][1];
  int start = blockIdx.x * VPB;
  int n = min(VPB, VEC_PER_BATCH - start);
  const float4* p=(const float4*)cube + (size_t)b*VEC_PER_BATCH + start;
  int i = threadIdx.x;
  for (; i + 3072 < n; i += 4096){
    float4 v0=p[i], v1=p[i+1024], v2=p[i+2048], v3=p[i+3072];
    h3add4(b,p0,p1,v0); h3add4(b,p0,p1,v1); h3add4(b,p0,p1,v2); h3add4(b,p0,p1,v3);
  }
  for (; i < n; i += 1024) h3add4(b,p0,p1,p[i]);
}

__global__ __launch_bounds__(256) void k_select3(){
  int b=blockIdx.x; int tid=threadIdx.x;
  __shared__ unsigned s[H3_BINS];
  __shared__ unsigned wq[8];
  __shared__ float vres[2];
  unsigned p0=g_sel2[b][0], p1=g_sel2[b][1];
  bool same = (p0==p1);
  int np = same?1:2;
  for (int p=0;p<np;p++){
    s[tid]=g_hist3[b][p][tid];
    __syncthreads();
    unsigned v=s[tid];
    unsigned inc=warp_iscan(v);
    if((tid&31)==31) wq[tid>>5]=inc;
    __syncthreads();
    if(tid==0){unsigned run=0; for(int k=0;k<8;k++){unsigned t=wq[k];wq[k]=run;run+=t;}}
    __syncthreads();
    unsigned excl = inc - v + wq[tid>>5];
    for (int j=0;j<2;j++){
      bool act = same ? (p==0) : (j==p);
      if (act){
        unsigned r = g_rem2[b][j];
        if (r>=excl && r<excl+v){
          vres[j]=__uint_as_float((g_sel2[b][j]<<8)|(unsigned)tid);
        }
      }
    }
    __syncthreads();
  }
  if (tid==0){
    const float pos = 0.9f * (float)(Nv-1);
    float frac = pos - floorf(pos);
    g_thr[b] = vres[0]*(1.0f-frac) + vres[1]*frac;
  }
}

// ---------------- fused compaction with decoupled lookback ----------------
__global__ __launch_bounds__(SC_THREADS) void k_scatter(const float* __restrict__ cube,
                                                        const float* __restrict__ dop,
                                                        float* __restrict__ out, int out_elems){
  __shared__ unsigned warpsum[16];
  __shared__ unsigned warpexcl[16];
  __shared__ unsigned s_agg;
  __shared__ unsigned s_gexcl;
  int b = blockIdx.y;
  float thr = g_thr[b];
  int tid = threadIdx.x, lane = tid & 31, wid = tid >> 5;

  // layout: block covers 4096 vec4s; warp w covers vec4s [w*256, w*256+256),
  // group j (0..7): vec4 index w*256 + j*32 + lane  -> perfectly coalesced.
  unsigned gvec0 = (unsigned)blockIdx.x*4096u + (unsigned)wid*256u;
  const float4* p = (const float4*)cube + (size_t)b*VEC_PER_BATCH + gvec0;

  float4 v[8];
  #pragma unroll
  for (int j=0;j<8;j++) v[j] = p[j*32 + lane];

  unsigned esc[8], gbase[8];
  unsigned run = 0;
  #pragma unroll
  for (int j=0;j<8;j++){
    unsigned c = (v[j].x>thr)+(v[j].y>thr)+(v[j].z>thr)+(v[j].w>thr);
    unsigned inc = c;
    #pragma unroll
    for (int d=1;d<32;d<<=1){ unsigned t=__shfl_up_sync(0xFFFFFFFFu,inc,d); if (lane>=d) inc+=t; }
    esc[j] = inc - c;
    gbase[j] = run;
    run += __shfl_sync(0xFFFFFFFFu, inc, 31);
  }
  if (lane==0) warpsum[wid] = run;
  __syncthreads();
  if (tid==0){
    unsigned acc=0;
    for (int k=0;k<16;k++){ unsigned t=warpsum[k]; warpexcl[k]=acc; acc+=t; }
    s_agg = acc;
  }
  __syncthreads();

  if (wid==0){
    unsigned agg = s_agg;
    unsigned excl = 0;
    int bx = blockIdx.x;
    if (bx == 0){
      if (lane==0) atomicExch(&g_part[b][0], (2ull<<62) | (unsigned long long)agg);
    } else {
      if (lane==0) atomicExch(&g_part[b][bx], (1ull<<62) | (unsigned long long)agg);
      unsigned running = 0;
      int j = bx - 1;
      while (true){
        int idx = j - lane;
        unsigned long long w; unsigned st;
        do {
          w = (idx >= 0) ? atomicAdd(&g_part[b][idx], 0ull) : (2ull<<62);
          st = (unsigned)(w>>62);
        } while (__any_sync(0xFFFFFFFFu, st==0u));
        unsigned val = (unsigned)(w & 0xFFFFFFFFull);
        unsigned bal = __ballot_sync(0xFFFFFFFFu, st==2u);
        if (bal){
          int f = __ffs(bal)-1;
          unsigned contrib = (lane<=f) ? val : 0u;
          #pragma unroll
          for (int d=16;d>0;d>>=1) contrib += __shfl_down_sync(0xFFFFFFFFu,contrib,d);
          running += __shfl_sync(0xFFFFFFFFu, contrib, 0);
          break;
        } else {
          unsigned contrib = val;
          #pragma unroll
          for (int d=16;d>0;d>>=1) contrib += __shfl_down_sync(0xFFFFFFFFu,contrib,d);
          running += __shfl_sync(0xFFFFFFFFu, contrib, 0);
          j -= 32;
        }
      }
      excl = running;
      if (lane==0) atomicExch(&g_part[b][bx], (2ull<<62) | (unsigned long long)(excl+agg));
    }
    if (lane==0){
      s_gexcl = excl;
      if (bx == SC_BLOCKS-1) g_total[b] = excl + agg;
    }
  }
  __syncthreads();

  unsigned warpbase = s_gexcl + warpexcl[wid];
  const float* dopb = dop + (size_t)b*Nv;
  #pragma unroll
  for (int j=0;j<8;j++){
    unsigned o = warpbase + gbase[j] + esc[j];
    unsigned gvec = gvec0 + (unsigned)j*32u + (unsigned)lane;
    float vals[4] = {v[j].x, v[j].y, v[j].z, v[j].w};
    #pragma unroll
    for (int c2=0;c2<4;c2++){
      if (vals[c2] > thr){
        unsigned gidx = gvec*4u + (unsigned)c2;
        unsigned z = gidx/(Yd*Xd);
        unsigned rem = gidx - z*(Yd*Xd);
        unsigned y = rem/Xd;
        unsigned x = rem - y*Xd;
        unsigned row = (unsigned)b*Kpad + o;
        float dv = dopb[gidx];
        size_t f = (size_t)row*5;
        if (f + 5 <= (size_t)out_elems){
          out[f+0] = ((float)x/320.0f)*72.0f;
          out[f+1] = ((float)y/320.0f)*32.0f;
          out[f+2] = ((float)z/40.0f)*8.0f;
          out[f+3] = vals[c2] / 10000000000000.0f;
          out[f+4] = dv - 1.9326f;
        }
        size_t ioff = (size_t)BKr*5 + (size_t)row*4;
        if (ioff + 4 <= (size_t)out_elems){
          out[ioff+0]=(float)b; out[ioff+1]=(float)z;
          out[ioff+2]=(float)y; out[ioff+3]=(float)x;
        }
        size_t voff = (size_t)BKr*9 + (size_t)row;
        if (voff < (size_t)out_elems) out[voff] = 1.0f;
        o++;
      }
    }
  }
}

// ---------------- zero only the invalid tail rows ----------------
__global__ __launch_bounds__(256) void k_cleanup(float* __restrict__ out, int out_elems){
  unsigned row = blockIdx.x*256u + threadIdx.x;
  if (row >= (unsigned)BKr) return;
  unsigned b = row / Kpad;
  unsigned r = row - b*Kpad;
  if (r < g_total[b]) return;
  size_t f = (size_t)row*5;
  if (f + 5 <= (size_t)out_elems){
    out[f+0]=0.f; out[f+1]=0.f; out[f+2]=0.f; out[f+3]=0.f; out[f+4]=0.f;
  }
  size_t ioff = (size_t)BKr*5 + (size_t)row*4;
  if (ioff + 4 <= (size_t)out_elems){
    out[ioff+0]=0.f; out[ioff+1]=0.f; out[ioff+2]=0.f; out[ioff+3]=0.f;
  }
  size_t voff = (size_t)BKr*9 + (size_t)row;
  if (voff < (size_t)out_elems) out[voff] = 0.f;
}

extern "C" void kernel_launch(void* const* d_in, const int* in_sizes, int n_in,
                              void* d_out, int out_size) {
  const float* cube = (const float*)d_in[0];
  const float* dop  = (const float*)d_in[1];
  float* out = (float*)d_out;

  // insurance: zero any tail beyond the 10*BKr floats we fully write
  if ((size_t)out_size > (size_t)BKr*10)
    cudaMemsetAsync(out + (size_t)BKr*10, 0,
                    ((size_t)out_size - (size_t)BKr*10)*sizeof(float));

  k_zero<<<32,1024>>>();

  dim3 gh(HV_BLOCKS, Bn);
  k_hist1<<<gh,1024>>>(cube);
  k_select1<<<Bn,1024>>>();
  k_hist2<<<gh,1024>>>(cube);
  k_select2<<<Bn,1024>>>();
  k_hist3<<<gh,1024>>>(cube);
  k_select3<<<Bn,256>>>();

  dim3 gs(SC_BLOCKS, Bn);
  k_scatter<<<gs,SC_THREADS>>>(cube, dop, out, out_size);
  k_cleanup<<<(BKr+255)/256,256>>>(out, out_size);
}